// round 4
// baseline (speedup 1.0000x reference)
#include <cuda_runtime.h>
#include <cuda_bf16.h>

// RandomLowRes2D: per-image (512x512 fp32) Gaussian blur (R=15, symmetric pad)
// + linear downsample (factor 1/res) + linear upsample back, along axis 0 or 1.
// Fully fused: one kernel, SMEM-staged lines, register sliding-window blur.

#define RR    15
#define HH    512
#define TL    8            // lines per CTA
#define LSTR  545          // buf line stride (512 + 2*15 = 542, padded odd)
#define SSTR  513          // s-buffer line stride (odd)
#define BLOCK 256

__global__ __launch_bounds__(BLOCK)
void lowres2d_kernel(const float* __restrict__ x,
                     const float* __restrict__ resolution,
                     const int*   __restrict__ axis,
                     const float* __restrict__ gap,
                     float* __restrict__ out)
{
    __shared__ float buf[TL * LSTR];     // input lines w/ halo; reused as output staging
    __shared__ float sbuf[TL * SSTR];    // blurred lines
    __shared__ float w[31];
    __shared__ float up_fr2[HH];
    __shared__ int   up_a[HH];
    __shared__ float dn_fr[HH];
    __shared__ int   dn_li[HH];

    const int img  = blockIdx.y;
    const int tid  = threadIdx.x;
    const int line0 = blockIdx.x * TL;

    const float res = resolution[img];
    const float gp  = gap[img];
    const int   ax  = axis[img];

    // sigma = (res * gap) * 1/sqrt(8 ln 2), clamped
    const float SIGC = 0.4246609001440095f;
    const float sig = fmaxf((res * gp) * SIGC, 1e-6f);

    // n_low = max(floor(512/res), 1)  -- exact fp32 division to match reference
    const int n_low = (int)fmaxf(floorf(__fdiv_rn(512.0f, res)), 1.0f);
    const float nlm1 = (float)n_low - 1.0f;

    const float* src = x   + (size_t)img * (HH * HH);
    float*       dst = out + (size_t)img * (HH * HH);

    // ---- load tile into SMEM (data at offset RR within each line) ----
    if (ax == 0) {
        // lines are columns: blur along H. element e = row, line l = column.
        for (int t = tid; t < TL * HH; t += BLOCK) {
            int l = t & (TL - 1);
            int e = t >> 3;
            buf[l * LSTR + RR + e] = src[e * HH + line0 + l];
        }
    } else {
        // lines are rows: blur along W.
        for (int t = tid; t < TL * HH; t += BLOCK) {
            int l = t >> 9;
            int e = t & (HH - 1);
            buf[l * LSTR + RR + e] = src[(line0 + l) * HH + e];
        }
    }

    // ---- per-image interpolation tables (shared across lines) ----
    for (int i = tid; i < HH; i += BLOCK) {
        float fi = (float)i;
        // upsample: pos2 = clip(i/res, 0, n_low-1)
        float pos2 = fminf(__fdiv_rn(fi, res), nlm1);
        float lo2  = floorf(pos2);
        up_fr2[i]  = pos2 - lo2;
        int a = (int)lo2;
        if (a > n_low - 1) a = n_low - 1;
        up_a[i] = a;
        // downsample: pos = clip(j*res, 0, 511)
        float pos = fminf(__fmul_rn(fi, res), 511.0f);
        float lo  = floorf(pos);
        dn_fr[i]  = pos - lo;
        dn_li[i]  = (int)lo;
    }

    // ---- Gaussian weights (warp 0) ----
    if (tid < 32) {
        float e = 0.0f;
        if (tid < 31) {
            float tt = __fdiv_rn((float)(tid - RR), sig);
            e = expf(-0.5f * tt * tt);
        }
        float s = e;
        #pragma unroll
        for (int o = 16; o > 0; o >>= 1) s += __shfl_xor_sync(0xffffffffu, s, o);
        if (tid < 31) w[tid] = __fdiv_rn(e, s);
    }
    __syncthreads();

    // ---- symmetric halo fill ----
    for (int t = tid; t < TL * 2 * RR; t += BLOCK) {
        int l = t / (2 * RR);
        int i = t - l * (2 * RR);
        float* b = buf + l * LSTR;
        if (i < RR) {
            b[i] = b[29 - i];                 // left: data(e), e<0 -> -e-1
        } else {
            int q = HH + RR + (i - RR);       // right: e in [512,526] -> 1023-e
            b[q] = b[1053 - q];
        }
    }
    __syncthreads();

    // ---- phase A: 31-tap blur, 8 outputs/thread via register window ----
    #pragma unroll
    for (int it = 0; it < (TL * HH / 8) / BLOCK; ++it) {
        int g  = tid + it * BLOCK;            // group id in [0, 512)
        int l  = g & (TL - 1);
        int r0 = (g >> 3) << 3;               // 8-aligned start within line
        const float* bb = buf + l * LSTR + r0;
        float win[38];
        #pragma unroll
        for (int m = 0; m < 38; ++m) win[m] = bb[m];
        float acc[8];
        #pragma unroll
        for (int u = 0; u < 8; ++u) acc[u] = 0.0f;
        #pragma unroll
        for (int k = 0; k < 31; ++k) {
            float wk = w[k];
            #pragma unroll
            for (int u = 0; u < 8; ++u) acc[u] = fmaf(wk, win[u + k], acc[u]);
        }
        float* so = sbuf + l * SSTR + r0;
        #pragma unroll
        for (int u = 0; u < 8; ++u) so[u] = acc[u];
    }
    __syncthreads();

    // ---- phase B: fused down+up sample; stage result back into buf ----
    for (int g = tid; g < TL * HH; g += BLOCK) {
        int l = g & (TL - 1);
        int i = g >> 3;
        int   a   = up_a[i];
        float fr2 = up_fr2[i];
        int   b2  = min(a + 1, n_low - 1);
        const float* sl = sbuf + l * SSTR;

        int   lia = dn_li[a];
        float fra = dn_fr[a];
        int   hia = min(lia + 1, HH - 1);
        float lowa = sl[lia] * (1.0f - fra) + sl[hia] * fra;

        int   lib = dn_li[b2];
        float frb = dn_fr[b2];
        int   hib = min(lib + 1, HH - 1);
        float lowb = sl[lib] * (1.0f - frb) + sl[hib] * frb;

        buf[l * LSTR + i] = lowa * (1.0f - fr2) + lowb * fr2;
    }
    __syncthreads();

    // ---- store (mirrors load pattern) ----
    if (ax == 0) {
        for (int t = tid; t < TL * HH; t += BLOCK) {
            int l = t & (TL - 1);
            int e = t >> 3;
            dst[e * HH + line0 + l] = buf[l * LSTR + e];
        }
    } else {
        for (int t = tid; t < TL * HH; t += BLOCK) {
            int l = t >> 9;
            int e = t & (HH - 1);
            dst[(line0 + l) * HH + e] = buf[l * LSTR + e];
        }
    }
}

extern "C" void kernel_launch(void* const* d_in, const int* in_sizes, int n_in,
                              void* d_out, int out_size)
{
    const float* x   = (const float*)d_in[0];
    const float* res = (const float*)d_in[1];
    const int*   ax  = (const int*)  d_in[2];
    const float* gp  = (const float*)d_in[3];
    float* out = (float*)d_out;

    int nimg = in_sizes[1];          // B*C = 64
    dim3 grid(HH / TL, nimg);        // (64, 64)
    lowres2d_kernel<<<grid, BLOCK>>>(x, res, ax, gp, out);
}

// round 7
// speedup vs baseline: 1.6224x; 1.6224x over previous
#include <cuda_runtime.h>
#include <cuda_bf16.h>

// RandomLowRes2D fused kernel, round 4:
//  - blur (31-tap, symmetric pad) with float4 window loads (conflict-free, stride 548)
//  - explicit low[] array (n_low entries/line) like the reference -> far fewer smem ops
//  - inline downsample math (no dn tables), packed float2 upsample table
//  - direct vectorized global stores (ax==1), staged transposed float4 stores (ax==0)

#define RR    15
#define HH    512
#define TL    8            // lines per CTA
#define LSTR  548          // buf line stride (floats); 548 % 32 == 4 -> conflict-free f4
#define DOFF  16           // data offset inside a buf line (16B aligned, room for halo)
#define SSTR  516          // s-buffer line stride; 516 % 32 == 4
#define BLOCK 256

__global__ __launch_bounds__(BLOCK)
void lowres2d_kernel(const float* __restrict__ x,
                     const float* __restrict__ resolution,
                     const int*   __restrict__ axis,
                     const float* __restrict__ gap,
                     float* __restrict__ out)
{
    __shared__ float  buf[TL * LSTR];    // input+halo; reused as low[] after blur
    __shared__ float  sbuf[TL * SSTR];   // blurred s; reused as ax0 output staging
    __shared__ float2 upt[HH];           // {a (bit-cast int), fr2} per output index
    __shared__ float  w[32];

    const int img   = blockIdx.y;
    const int tid   = threadIdx.x;
    const int line0 = blockIdx.x * TL;

    const float res = resolution[img];
    const float gp  = gap[img];
    const int   ax  = axis[img];

    const float SIGC = 0.4246609001440095f;          // 1/sqrt(8 ln 2)
    const float sig  = fmaxf((res * gp) * SIGC, 1e-6f);

    const int   n_low = (int)fmaxf(floorf(__fdiv_rn(512.0f, res)), 1.0f);
    const float nlm1  = (float)n_low - 1.0f;

    const float* src = x   + (size_t)img * (HH * HH);
    float*       dst = out + (size_t)img * (HH * HH);

    // ---- load tile into SMEM (vectorized) ----
    if (ax == 0) {
        // lines are image columns; element index e = row
        for (int t = tid; t < 1024; t += BLOCK) {
            int e = t >> 1;
            int h = t & 1;
            float4 v = *(const float4*)(src + e * HH + line0 + 4 * h);
            buf[(4 * h + 0) * LSTR + DOFF + e] = v.x;
            buf[(4 * h + 1) * LSTR + DOFF + e] = v.y;
            buf[(4 * h + 2) * LSTR + DOFF + e] = v.z;
            buf[(4 * h + 3) * LSTR + DOFF + e] = v.w;
        }
    } else {
        // lines are image rows
        for (int t = tid; t < 1024; t += BLOCK) {
            int l  = t >> 7;
            int e4 = (t & 127) << 2;
            *(float4*)&buf[l * LSTR + DOFF + e4] =
                *(const float4*)(src + (line0 + l) * HH + e4);
        }
    }

    // ---- upsample table: pos2 = clip(i/res, 0, n_low-1) ----
    for (int i = tid; i < HH; i += BLOCK) {
        float pos2 = fminf(__fdiv_rn((float)i, res), nlm1);
        float lo2  = floorf(pos2);
        int   a    = min((int)lo2, n_low - 1);
        upt[i] = make_float2(__int_as_float(a), pos2 - lo2);
    }

    // ---- Gaussian weights (warp 0) ----
    if (tid < 32) {
        float e = 0.0f;
        if (tid < 31) {
            float tt = __fdiv_rn((float)(tid - RR), sig);
            e = expf(-0.5f * tt * tt);
        }
        float s = e;
        #pragma unroll
        for (int o = 16; o > 0; o >>= 1) s += __shfl_xor_sync(0xffffffffu, s, o);
        if (tid < 31) w[tid] = __fdiv_rn(e, s);
    }

    // ---- symmetric halo ----
    __syncthreads();
    for (int t = tid; t < TL * 2 * RR; t += BLOCK) {
        int l = t / (2 * RR);
        int i = t - l * (2 * RR);
        float* b = buf + l * LSTR;
        if (i < RR) {
            b[DOFF - 1 - i] = b[DOFF + i];                 // left mirror
        } else {
            int j = i - RR;
            b[DOFF + HH + j] = b[DOFF + HH - 1 - j];       // right mirror
        }
    }
    __syncthreads();

    // ---- blur: 8 outputs/thread, float4 window loads ----
    #pragma unroll
    for (int it = 0; it < 2; ++it) {
        int g  = tid + it * BLOCK;          // [0, 512)
        int l  = g & (TL - 1);
        int r0 = (g >> 3) << 3;             // 8-aligned output start
        // window covers ext positions [r0-16, r0+24): buf index DOFF + r0 - 16
        const float* bp = buf + l * LSTR + r0;   // = &buf[l*LSTR + DOFF + r0 - 16]
        float win[40];
        #pragma unroll
        for (int m = 0; m < 10; ++m)
            *(float4*)&win[4 * m] = *(const float4*)(bp + 4 * m);
        float acc[8];
        #pragma unroll
        for (int u = 0; u < 8; ++u) acc[u] = 0.0f;
        #pragma unroll
        for (int k = 0; k < 31; ++k) {
            float wk = w[k];
            #pragma unroll
            for (int u = 0; u < 8; ++u)
                acc[u] = fmaf(wk, win[u + k + 1], acc[u]);
        }
        float* so = sbuf + l * SSTR + r0;
        #pragma unroll
        for (int m = 0; m < 2; ++m)
            *(float4*)&so[4 * m]     = make_float4(acc[4*m], acc[4*m+1], acc[4*m+2], acc[4*m+3]);
    }
    __syncthreads();

    // ---- low-build: low[j] = lerp(s, j*res), j < n_low; stored into buf ----
    {
        int total = TL * n_low;
        for (int t = tid; t < total; t += BLOCK) {
            int l = t & (TL - 1);
            int j = t >> 3;
            float pos = fminf(__fmul_rn((float)j, res), 511.0f);
            float lo  = floorf(pos);
            float fr  = pos - lo;
            int   li  = (int)lo;
            int   hi  = min(li + 1, HH - 1);
            const float* sl = sbuf + l * SSTR;
            buf[l * LSTR + j] = sl[li] * (1.0f - fr) + sl[hi] * fr;
        }
    }
    __syncthreads();

    // ---- upsample + store ----
    if (ax == 1) {
        // direct vectorized store: dst[(line0+l)*HH + i]
        for (int t = tid; t < 1024; t += BLOCK) {
            int l  = t >> 7;
            int i0 = (t & 127) << 2;
            const float* lw = buf + l * LSTR;
            float4 o;
            #pragma unroll
            for (int q = 0; q < 4; ++q) {
                float2 u  = upt[i0 + q];
                int    a  = __float_as_int(u.x);
                float  f2 = u.y;
                int    b2 = min(a + 1, n_low - 1);
                float  v  = lw[a] * (1.0f - f2) + lw[b2] * f2;
                ((float*)&o)[q] = v;
            }
            *(float4*)(dst + (line0 + l) * HH + i0) = o;
        }
    } else {
        // compute into sbuf staging, then transposed vectorized store
        for (int t = tid; t < 1024; t += BLOCK) {
            int l  = t >> 7;
            int i0 = (t & 127) << 2;
            const float* lw = buf + l * LSTR;
            float* so = sbuf + l * SSTR;
            #pragma unroll
            for (int q = 0; q < 4; ++q) {
                float2 u  = upt[i0 + q];
                int    a  = __float_as_int(u.x);
                float  f2 = u.y;
                int    b2 = min(a + 1, n_low - 1);
                so[i0 + q] = lw[a] * (1.0f - f2) + lw[b2] * f2;
            }
        }
        __syncthreads();
        for (int t = tid; t < 1024; t += BLOCK) {
            int e = t >> 1;
            int h = t & 1;
            float4 v;
            v.x = sbuf[(4 * h + 0) * SSTR + e];
            v.y = sbuf[(4 * h + 1) * SSTR + e];
            v.z = sbuf[(4 * h + 2) * SSTR + e];
            v.w = sbuf[(4 * h + 3) * SSTR + e];
            *(float4*)(dst + e * HH + line0 + 4 * h) = v;
        }
    }
}

extern "C" void kernel_launch(void* const* d_in, const int* in_sizes, int n_in,
                              void* d_out, int out_size)
{
    const float* x   = (const float*)d_in[0];
    const float* res = (const float*)d_in[1];
    const int*   ax  = (const int*)  d_in[2];
    const float* gp  = (const float*)d_in[3];
    float* out = (float*)d_out;

    int nimg = in_sizes[1];          // B*C = 64
    dim3 grid(HH / TL, nimg);        // (64, 64)
    lowres2d_kernel<<<grid, BLOCK>>>(x, res, ax, gp, out);
}